// round 8
// baseline (speedup 1.0000x reference)
#include <cuda_runtime.h>
#include <cstdint>

#define NNODE 100000
#define NEDGE 3200000
#define FIN   128
#define HDIM  32
#define MHDIM 64
#define NCLS  10
#define NGRAPH 64
#define NBLK  ((NNODE + 255) / 256)   // 391

// ---------------- device scratch (static, no allocation) ----------------
__device__ float    g_deg[NNODE];
__device__ float    g_dinv[NNODE];
__device__ int      g_cntD[NNODE];
__device__ int      g_ptrD[NNODE + 1];
__device__ int2     g_eD[NEDGE];          // (src, weight-bits) packed
__device__ unsigned g_state[NBLK];        // decoupled-lookback states
__device__ float    g_tA[(size_t)NNODE * HDIM];
__device__ float    g_tB[(size_t)NNODE * HDIM];
__device__ float    g_h[(size_t)NNODE * HDIM];
__device__ float    g_pool[NGRAPH * HDIM];
__device__ float    g_cntg[NGRAPH];
__device__ int      g_is64;

// ---------------- init + dtype detect (fused, fully parallel) ----------------
__global__ void init_kernel(const void* ei) {
    int i = blockIdx.x * blockDim.x + threadIdx.x;
    if (i < NNODE) {
        g_deg[i] = 1.0f;   // self-loop weight 1
        g_cntD[i] = 0;
    }
    if (i < NBLK) g_state[i] = 0u;
    if (i < NGRAPH * HDIM) g_pool[i] = 0.0f;
    if (i < NGRAPH) g_cntg[i] = 0.0f;
    if (i == 0) g_ptrD[NNODE] = NEDGE;
    // warp 0 of block 0: parallel int64-vs-int32 detection.
    if (blockIdx.x == 0 && threadIdx.x < 32) {
        const long long* p = (const long long*)ei;
        int bad = 0;
        #pragma unroll
        for (int k = 0; k < 4; k++) {
            long long v = p[(threadIdx.x * 4 + k) * 5 + 1];
            if (v < 0 || v >= NNODE) bad = 1;
        }
        unsigned m = __ballot_sync(0xffffffffu, bad);
        if (threadIdx.x == 0) g_is64 = (m == 0u);
    }
}

// ---------------- histogram of destinations + weighted degree (x4 vec) ------
__global__ void hist_kernel(const void* ei, const float* __restrict__ ew) {
    int t = blockIdx.x * blockDim.x + threadIdx.x;   // 0 .. NEDGE/4-1
    if (t >= NEDGE / 4) return;
    int c0, c1, c2, c3;
    if (g_is64) {
        const longlong2* p = (const longlong2*)((const long long*)ei + NEDGE) + (size_t)t * 2;
        longlong2 a = p[0], b = p[1];
        c0 = (int)a.x; c1 = (int)a.y; c2 = (int)b.x; c3 = (int)b.y;
    } else {
        int4 v = ((const int4*)((const int*)ei + NEDGE))[t];
        c0 = v.x; c1 = v.y; c2 = v.z; c3 = v.w;
    }
    float4 w = ((const float4*)ew)[t];
    atomicAdd(&g_cntD[c0], 1); atomicAdd(&g_deg[c0], w.x);
    atomicAdd(&g_cntD[c1], 1); atomicAdd(&g_deg[c1], w.y);
    atomicAdd(&g_cntD[c2], 1); atomicAdd(&g_deg[c2], w.z);
    atomicAdd(&g_cntD[c3], 1); atomicAdd(&g_deg[c3], w.w);
}

// ---------------- single-pass scan: decoupled lookback ----------------
// state = (flag<<30)|value ; flag: 1 = aggregate ready, 2 = inclusive prefix ready
__global__ void scan_kernel() {
    __shared__ int ws[8];
    __shared__ int s_prefix;
    int b = blockIdx.x, tid = threadIdx.x;
    int i = b * 256 + tid;
    int v = (i < NNODE) ? g_cntD[i] : 0;
    int lane = tid & 31, wid = tid >> 5;
    int x = v;
    #pragma unroll
    for (int o = 1; o < 32; o <<= 1) {
        int y = __shfl_up_sync(0xffffffffu, x, o);
        if (lane >= o) x += y;
    }
    if (lane == 31) ws[wid] = x;
    __syncthreads();
    if (wid == 0 && lane < 8) {
        int s = ws[lane];
        #pragma unroll
        for (int o = 1; o < 8; o <<= 1) {
            int y = __shfl_up_sync(0x000000ffu, s, o);
            if (lane >= o) s += y;
        }
        ws[lane] = s;
    }
    __syncthreads();
    int woff = (wid > 0) ? ws[wid - 1] : 0;
    int total = ws[7];

    if (wid == 0) {
        if (b == 0) {
            if (lane == 0) {
                atomicExch(&g_state[0], (2u << 30) | (unsigned)total);
                s_prefix = 0;
            }
        } else {
            if (lane == 0) atomicExch(&g_state[b], (1u << 30) | (unsigned)total);
            int prefix = 0, base = b - 1;
            bool done = false;
            while (!done) {
                int idx = base - lane;
                unsigned s = (2u << 30);             // idx<0 => prefix 0
                for (;;) {
                    if (idx >= 0) s = *(volatile unsigned*)&g_state[idx];
                    unsigned ready = __ballot_sync(0xffffffffu, (s >> 30) != 0u);
                    if (ready == 0xffffffffu) break;
                }
                unsigned m2 = __ballot_sync(0xffffffffu, (s >> 30) == 2u);
                int stop = (m2 != 0u) ? (__ffs(m2) - 1) : 32;
                int val = (idx >= 0 && lane <= stop) ? (int)(s & 0x3FFFFFFFu) : 0;
                #pragma unroll
                for (int o = 16; o > 0; o >>= 1)
                    val += __shfl_down_sync(0xffffffffu, val, o);
                if (lane == 0) prefix += val;
                done = (m2 != 0u);
                base -= 32;
            }
            if (lane == 0) {
                atomicExch(&g_state[b], (2u << 30) | (unsigned)(prefix + total));
                s_prefix = prefix;
            }
        }
    }
    __syncthreads();
    int excl = s_prefix + woff + x - v;
    if (i < NNODE) {
        g_ptrD[i] = excl;
        g_cntD[i] = 0;
        g_dinv[i] = rsqrtf(g_deg[i]);   // deg >= 1 always
    }
}

// ---------------- fill CSR-by-destination, packed (src, w) ----------------
__global__ void fill_kernel(const void* ei, const float* __restrict__ ew) {
    int t = blockIdx.x * blockDim.x + threadIdx.x;   // 0 .. NEDGE/4-1
    if (t >= NEDGE / 4) return;
    int r[4], c[4];
    if (g_is64) {
        const longlong2* pr = (const longlong2*)((const long long*)ei) + (size_t)t * 2;
        const longlong2* pc = (const longlong2*)((const long long*)ei + NEDGE) + (size_t)t * 2;
        longlong2 a = pr[0], b = pr[1];
        r[0] = (int)a.x; r[1] = (int)a.y; r[2] = (int)b.x; r[3] = (int)b.y;
        a = pc[0]; b = pc[1];
        c[0] = (int)a.x; c[1] = (int)a.y; c[2] = (int)b.x; c[3] = (int)b.y;
    } else {
        int4 v = ((const int4*)((const int*)ei))[t];
        r[0] = v.x; r[1] = v.y; r[2] = v.z; r[3] = v.w;
        v = ((const int4*)((const int*)ei + NEDGE))[t];
        c[0] = v.x; c[1] = v.y; c[2] = v.z; c[3] = v.w;
    }
    float4 w4 = ((const float4*)ew)[t];
    float wv[4] = {w4.x, w4.y, w4.z, w4.w};
    #pragma unroll
    for (int k = 0; k < 4; k++) {
        float nw = g_dinv[r[k]] * wv[k] * g_dinv[c[k]];
        int pos = g_ptrD[c[k]] + atomicAdd(&g_cntD[c[k]], 1);
        g_eD[pos] = make_int2(r[k], __float_as_int(nw));
    }
}

// ---------------- GEMM1: t = x[N,128] @ W1[128,32] ----------------
__global__ void gemm1_kernel(const float* __restrict__ A, const float* __restrict__ W,
                             float* __restrict__ out) {
    constexpr int K = FIN;
    constexpr int PAD = 4;
    __shared__ float sW[K * 32];
    __shared__ float sA[64 * (K + PAD)];
    int tid = threadIdx.x;        // 256 threads
    int rb = blockIdx.x * 64;

    for (int i = tid; i < K * 8; i += 256)
        ((float4*)sW)[i] = ((const float4*)W)[i];

    int tc = tid & 7;
    int trp = tid >> 3;
    int r0 = trp * 2, r1 = r0 + 1;
    float acc[2][4] = {};

    for (int i = tid; i < 64 * K / 4; i += 256) {
        int r = i / (K / 4);
        int c4 = i % (K / 4);
        float4 v = make_float4(0.f, 0.f, 0.f, 0.f);
        if (rb + r < NNODE)
            v = *(const float4*)(A + (size_t)(rb + r) * K + c4 * 4);
        *(float4*)(sA + r * (K + PAD) + c4 * 4) = v;
    }
    __syncthreads();
    #pragma unroll 8
    for (int k = 0; k < K; k++) {
        float a0 = sA[r0 * (K + PAD) + k];
        float a1 = sA[r1 * (K + PAD) + k];
        float4 w = ((const float4*)sW)[k * 8 + tc];
        acc[0][0] += a0 * w.x; acc[0][1] += a0 * w.y;
        acc[0][2] += a0 * w.z; acc[0][3] += a0 * w.w;
        acc[1][0] += a1 * w.x; acc[1][1] += a1 * w.y;
        acc[1][2] += a1 * w.z; acc[1][3] += a1 * w.w;
    }
    #pragma unroll
    for (int rr = 0; rr < 2; rr++) {
        int r = rb + r0 + rr;
        if (r < NNODE) {
            float4 v = make_float4(acc[rr][0], acc[rr][1], acc[rr][2], acc[rr][3]);
            *(float4*)(out + (size_t)r * 32 + tc * 4) = v;
        }
    }
}

// ---------------- aggregation: warp/node, 8 edges in flight ----------------
// lane = (edge-group g = lane>>2, feature-quad q = lane&3); each lane loads
// 2 independent float4 (features 4q.. and 16+4q..) => 16 LDG.128/warp in flight
// MODE 0: h = relu(agg + bias); write t_next = h @ Wn to tout
// MODE 1: write agg + bias (no relu) to hout
template <int MODE>
__global__ void agg_kernel(const float* __restrict__ tin,
                           const float* __restrict__ bias,
                           const float* __restrict__ Wn,
                           float* __restrict__ tout,
                           float* __restrict__ hout) {
    __shared__ float s_row[8][32];
    int warp = threadIdx.x >> 5, lane = threadIdx.x & 31;
    int w = blockIdx.x * 8 + warp;
    int q = lane & 3, g = lane >> 2;

    float wcol[32];
    if (MODE == 0) {
        #pragma unroll
        for (int f = 0; f < 32; f++) wcol[f] = Wn[f * 32 + lane];
    }
    if (w >= NNODE) return;

    const float4* tin4 = (const float4*)tin;
    int p0 = g_ptrD[w], p1 = g_ptrD[w + 1];
    float4 accA = make_float4(0.f, 0.f, 0.f, 0.f);
    float4 accB = make_float4(0.f, 0.f, 0.f, 0.f);
    if (g == 0) {                         // self-loop on edge-group 0
        float dv = g_dinv[w];
        float s = dv * dv;
        float4 fa = __ldg(&tin4[(size_t)w * 8 + q]);
        float4 fb = __ldg(&tin4[(size_t)w * 8 + q + 4]);
        accA.x = s * fa.x; accA.y = s * fa.y; accA.z = s * fa.z; accA.w = s * fa.w;
        accB.x = s * fb.x; accB.y = s * fb.y; accB.z = s * fb.z; accB.w = s * fb.w;
    }
    for (int p = p0 + g; p < p1; p += 8) {
        int2 ev = __ldg(&g_eD[p]);        // 4-lane broadcast; warp reads 64B coalesced
        float ww = __int_as_float(ev.y);
        float4 fa = __ldg(&tin4[(size_t)ev.x * 8 + q]);
        float4 fb = __ldg(&tin4[(size_t)ev.x * 8 + q + 4]);
        accA.x += ww * fa.x; accA.y += ww * fa.y; accA.z += ww * fa.z; accA.w += ww * fa.w;
        accB.x += ww * fb.x; accB.y += ww * fb.y; accB.z += ww * fb.z; accB.w += ww * fb.w;
    }
    // reduce across the 8 edge-groups (lanes q, q+4, ..., q+28)
    #pragma unroll
    for (int o = 16; o >= 4; o >>= 1) {
        accA.x += __shfl_down_sync(0xffffffffu, accA.x, o);
        accA.y += __shfl_down_sync(0xffffffffu, accA.y, o);
        accA.z += __shfl_down_sync(0xffffffffu, accA.z, o);
        accA.w += __shfl_down_sync(0xffffffffu, accA.w, o);
        accB.x += __shfl_down_sync(0xffffffffu, accB.x, o);
        accB.y += __shfl_down_sync(0xffffffffu, accB.y, o);
        accB.z += __shfl_down_sync(0xffffffffu, accB.z, o);
        accB.w += __shfl_down_sync(0xffffffffu, accB.w, o);
    }
    if (g == 0) {
        const float4* b4 = (const float4*)bias;
        float4 ba = __ldg(&b4[q]), bb = __ldg(&b4[q + 4]);
        accA.x += ba.x; accA.y += ba.y; accA.z += ba.z; accA.w += ba.w;
        accB.x += bb.x; accB.y += bb.y; accB.z += bb.z; accB.w += bb.w;
        if (MODE == 0) {
            accA.x = fmaxf(accA.x, 0.f); accA.y = fmaxf(accA.y, 0.f);
            accA.z = fmaxf(accA.z, 0.f); accA.w = fmaxf(accA.w, 0.f);
            accB.x = fmaxf(accB.x, 0.f); accB.y = fmaxf(accB.y, 0.f);
            accB.z = fmaxf(accB.z, 0.f); accB.w = fmaxf(accB.w, 0.f);
            *(float4*)&s_row[warp][q * 4]      = accA;
            *(float4*)&s_row[warp][16 + q * 4] = accB;
        } else {
            ((float4*)hout)[(size_t)w * 8 + q]     = accA;
            ((float4*)hout)[(size_t)w * 8 + q + 4] = accB;
        }
    }
    if (MODE == 0) {
        __syncwarp();
        float o = 0.f;
        #pragma unroll
        for (int f = 0; f < 32; f++) o += s_row[warp][f] * wcol[f];
        tout[(size_t)w * 32 + lane] = o;
    }
}

// ---------------- mean pool (batch is sorted) ----------------
__global__ void pool_kernel(const float* __restrict__ h, const void* batch) {
    int gtid = blockIdx.x * blockDim.x + threadIdx.x;
    int w = gtid >> 5, lane = gtid & 31;
    int n0 = w * 32;
    if (n0 >= NNODE) return;
    int is64 = g_is64;
    int n1 = (n0 + 32 < NNODE) ? n0 + 32 : NNODE;
    float acc = 0.f; int curg = -1; int run = 0;
    for (int i = n0; i < n1; i++) {
        int gg = is64 ? (int)((const long long*)batch)[i] : ((const int*)batch)[i];
        if (gg != curg) {
            if (curg >= 0) {
                atomicAdd(&g_pool[curg * 32 + lane], acc);
                if (lane == 0) atomicAdd(&g_cntg[curg], (float)run);
            }
            curg = gg; acc = 0.f; run = 0;
        }
        acc += h[(size_t)i * 32 + lane];
        run++;
    }
    if (curg >= 0) {
        atomicAdd(&g_pool[curg * 32 + lane], acc);
        if (lane == 0) atomicAdd(&g_cntg[curg], (float)run);
    }
}

// ---------------- tiny MLP head, single block, smem-staged weights ----------
__global__ void mlp_kernel(const float* __restrict__ Wm0, const float* __restrict__ bm0,
                           const float* __restrict__ Wm1, const float* __restrict__ bm1,
                           const float* __restrict__ Wout, const float* __restrict__ bout,
                           float* __restrict__ out) {
    __shared__ float sg[NGRAPH * HDIM];
    __shared__ float sm0[NGRAPH * MHDIM];
    __shared__ float sm1[NGRAPH * MHDIM];
    __shared__ float sW0[HDIM * MHDIM];
    __shared__ float sW1[MHDIM * MHDIM];
    __shared__ float sWo[MHDIM * NCLS];
    int tid = threadIdx.x;      // 256
    for (int i = tid; i < HDIM * MHDIM; i += 256) sW0[i] = Wm0[i];
    for (int i = tid; i < MHDIM * MHDIM; i += 256) sW1[i] = Wm1[i];
    for (int i = tid; i < MHDIM * NCLS; i += 256) sWo[i] = Wout[i];
    for (int i = tid; i < NGRAPH * HDIM; i += 256) {
        int gg = i / HDIM;
        sg[i] = g_pool[i] / fmaxf(g_cntg[gg], 1.0f);
    }
    __syncthreads();
    for (int i = tid; i < NGRAPH * MHDIM; i += 256) {
        int gg = i / MHDIM, j = i % MHDIM;
        float s = bm0[j];
        #pragma unroll
        for (int f = 0; f < HDIM; f++) s += sg[gg * HDIM + f] * sW0[f * MHDIM + j];
        sm0[i] = fmaxf(s, 0.f);
    }
    __syncthreads();
    for (int i = tid; i < NGRAPH * MHDIM; i += 256) {
        int gg = i / MHDIM, j = i % MHDIM;
        float s = bm1[j];
        #pragma unroll
        for (int f = 0; f < MHDIM; f++) s += sm0[gg * MHDIM + f] * sW1[f * MHDIM + j];
        sm1[i] = fmaxf(s, 0.f);
    }
    __syncthreads();
    for (int i = tid; i < NGRAPH * NCLS; i += 256) {
        int gg = i / NCLS, cc = i % NCLS;
        float s = bout[cc];
        #pragma unroll
        for (int j = 0; j < MHDIM; j++) s += sm1[gg * MHDIM + j] * sWo[j * NCLS + cc];
        out[i] = s;
    }
}

// ---------------- launch ----------------
extern "C" void kernel_launch(void* const* d_in, const int* in_sizes, int n_in,
                              void* d_out, int out_size) {
    const float* x    = (const float*)d_in[0];
    const void*  ei   = d_in[1];
    const float* ew   = (const float*)d_in[2];
    const void*  batch= d_in[3];
    const float* W1   = (const float*)d_in[4];
    const float* b1   = (const float*)d_in[5];
    const float* W2   = (const float*)d_in[6];
    const float* b2   = (const float*)d_in[7];
    const float* W3   = (const float*)d_in[8];
    const float* b3   = (const float*)d_in[9];
    const float* Wm0  = (const float*)d_in[10];
    const float* bm0  = (const float*)d_in[11];
    const float* Wm1  = (const float*)d_in[12];
    const float* bm1  = (const float*)d_in[13];
    const float* Wout = (const float*)d_in[14];
    const float* bout = (const float*)d_in[15];
    float* out = (float*)d_out;

    float *tA, *tB, *h_ptr;
    cudaGetSymbolAddress((void**)&tA, g_tA);
    cudaGetSymbolAddress((void**)&tB, g_tB);
    cudaGetSymbolAddress((void**)&h_ptr, g_h);

    const int EB4 = (NEDGE / 4 + 255) / 256;     // 3125
    const int NB  = NBLK;                         // 391
    const int GB  = (NNODE + 63) / 64;            // 1563
    const int AB  = (NNODE + 7) / 8;              // 12500

    init_kernel<<<NB, 256>>>(ei);                            // 1
    hist_kernel<<<EB4, 256>>>(ei, ew);                       // 2
    scan_kernel<<<NB, 256>>>();                              // 3
    fill_kernel<<<EB4, 256>>>(ei, ew);                       // 4  <- ncu slot

    gemm1_kernel<<<GB, 256>>>(x, W1, tA);                    // 5
    agg_kernel<0><<<AB, 256>>>(tA, b1, W2, tB, nullptr);     // 6
    agg_kernel<0><<<AB, 256>>>(tB, b2, W3, tA, nullptr);     // 7
    agg_kernel<1><<<AB, 256>>>(tA, b3, nullptr, nullptr, h_ptr); // 8

    pool_kernel<<<NB, 256>>>(h_ptr, batch);                  // 9
    mlp_kernel<<<1, 256>>>(Wm0, bm0, Wm1, bm1, Wout, bout, out); // 10
}

// round 10
// speedup vs baseline: 1.1048x; 1.1048x over previous
#include <cuda_runtime.h>
#include <cstdint>

#define NNODE 100000
#define NEDGE 3200000
#define FIN   128
#define HDIM  32
#define MHDIM 64
#define NCLS  10
#define NGRAPH 64
#define NBLK  ((NNODE + 255) / 256)   // 391

// ---------------- device scratch (static, no allocation) ----------------
__device__ unsigned long long g_degCnt[NNODE];  // (count<<32) | fixed-point deg (2^20)
__device__ float    g_dinv[NNODE];
__device__ int      g_cntD[NNODE];
__device__ int      g_ptrD[NNODE + 1];
__device__ int2     g_eD[NEDGE];          // (src, weight-bits) packed
__device__ unsigned g_state[NBLK];        // decoupled-lookback states
__device__ float    g_tA[(size_t)NNODE * HDIM];
__device__ float    g_tB[(size_t)NNODE * HDIM];
__device__ float    g_h[(size_t)NNODE * HDIM];
__device__ float    g_pool[NGRAPH * HDIM];
__device__ float    g_cntg[NGRAPH];
__device__ int      g_is64;

// ---------------- init + dtype detect (fused, fully parallel) ----------------
__global__ void init_kernel(const void* ei) {
    int i = blockIdx.x * blockDim.x + threadIdx.x;
    if (i < NNODE) {
        g_degCnt[i] = (1ull << 20);   // count=0, deg=1.0 (self-loop weight)
        g_cntD[i] = 0;
    }
    if (i < NBLK) g_state[i] = 0u;
    if (i < NGRAPH * HDIM) g_pool[i] = 0.0f;
    if (i < NGRAPH) g_cntg[i] = 0.0f;
    if (i == 0) g_ptrD[NNODE] = NEDGE;
    // warp 0 of block 0: parallel int64-vs-int32 detection.
    if (blockIdx.x == 0 && threadIdx.x < 32) {
        const long long* p = (const long long*)ei;
        int bad = 0;
        #pragma unroll
        for (int k = 0; k < 4; k++) {
            long long v = p[(threadIdx.x * 4 + k) * 5 + 1];
            if (v < 0 || v >= NNODE) bad = 1;
        }
        unsigned m = __ballot_sync(0xffffffffu, bad);
        if (threadIdx.x == 0) g_is64 = (m == 0u);
    }
}

// ---- histogram: ONE packed 64-bit atomic per edge (count + fixed deg) ------
__global__ void hist_kernel(const void* ei, const float* __restrict__ ew) {
    int t = blockIdx.x * blockDim.x + threadIdx.x;   // 0 .. NEDGE/4-1
    if (t >= NEDGE / 4) return;
    int c0, c1, c2, c3;
    if (g_is64) {
        const longlong2* p = (const longlong2*)((const long long*)ei + NEDGE) + (size_t)t * 2;
        longlong2 a = p[0], b = p[1];
        c0 = (int)a.x; c1 = (int)a.y; c2 = (int)b.x; c3 = (int)b.y;
    } else {
        int4 v = ((const int4*)((const int*)ei + NEDGE))[t];
        c0 = v.x; c1 = v.y; c2 = v.z; c3 = v.w;
    }
    float4 w = ((const float4*)ew)[t];
    atomicAdd(&g_degCnt[c0], (1ull << 32) + (unsigned long long)(w.x * 1048576.0f + 0.5f));
    atomicAdd(&g_degCnt[c1], (1ull << 32) + (unsigned long long)(w.y * 1048576.0f + 0.5f));
    atomicAdd(&g_degCnt[c2], (1ull << 32) + (unsigned long long)(w.z * 1048576.0f + 0.5f));
    atomicAdd(&g_degCnt[c3], (1ull << 32) + (unsigned long long)(w.w * 1048576.0f + 0.5f));
}

// ---------------- single-pass scan: decoupled lookback ----------------
// state = (flag<<30)|value ; flag: 1 = aggregate ready, 2 = inclusive prefix ready
__global__ void scan_kernel() {
    __shared__ int ws[8];
    __shared__ int s_prefix;
    int b = blockIdx.x, tid = threadIdx.x;
    int i = b * 256 + tid;
    int v = 0; float deg = 1.0f;
    if (i < NNODE) {
        unsigned long long pk = g_degCnt[i];
        v = (int)(pk >> 32);
        deg = (float)(pk & 0xffffffffull) * (1.0f / 1048576.0f);
    }
    int lane = tid & 31, wid = tid >> 5;
    int x = v;
    #pragma unroll
    for (int o = 1; o < 32; o <<= 1) {
        int y = __shfl_up_sync(0xffffffffu, x, o);
        if (lane >= o) x += y;
    }
    if (lane == 31) ws[wid] = x;
    __syncthreads();
    if (wid == 0 && lane < 8) {
        int s = ws[lane];
        #pragma unroll
        for (int o = 1; o < 8; o <<= 1) {
            int y = __shfl_up_sync(0x000000ffu, s, o);
            if (lane >= o) s += y;
        }
        ws[lane] = s;
    }
    __syncthreads();
    int woff = (wid > 0) ? ws[wid - 1] : 0;
    int total = ws[7];

    if (wid == 0) {
        if (b == 0) {
            if (lane == 0) {
                atomicExch(&g_state[0], (2u << 30) | (unsigned)total);
                s_prefix = 0;
            }
        } else {
            if (lane == 0) atomicExch(&g_state[b], (1u << 30) | (unsigned)total);
            int prefix = 0, base = b - 1;
            bool done = false;
            while (!done) {
                int idx = base - lane;
                unsigned s = (2u << 30);             // idx<0 => prefix 0
                for (;;) {
                    if (idx >= 0) s = *(volatile unsigned*)&g_state[idx];
                    unsigned ready = __ballot_sync(0xffffffffu, (s >> 30) != 0u);
                    if (ready == 0xffffffffu) break;
                }
                unsigned m2 = __ballot_sync(0xffffffffu, (s >> 30) == 2u);
                int stop = (m2 != 0u) ? (__ffs(m2) - 1) : 32;
                int val = (idx >= 0 && lane <= stop) ? (int)(s & 0x3FFFFFFFu) : 0;
                #pragma unroll
                for (int o = 16; o > 0; o >>= 1)
                    val += __shfl_down_sync(0xffffffffu, val, o);
                if (lane == 0) prefix += val;
                done = (m2 != 0u);
                base -= 32;
            }
            if (lane == 0) {
                atomicExch(&g_state[b], (2u << 30) | (unsigned)(prefix + total));
                s_prefix = prefix;
            }
        }
    }
    __syncthreads();
    int excl = s_prefix + woff + x - v;
    if (i < NNODE) {
        g_ptrD[i] = excl;
        g_dinv[i] = rsqrtf(deg);   // deg >= 1 always
    }
}

// ---------------- fill CSR-by-destination, packed (src, w) ----------------
__global__ void fill_kernel(const void* ei, const float* __restrict__ ew) {
    int t = blockIdx.x * blockDim.x + threadIdx.x;   // 0 .. NEDGE/4-1
    if (t >= NEDGE / 4) return;
    int r[4], c[4];
    if (g_is64) {
        const longlong2* pr = (const longlong2*)((const long long*)ei) + (size_t)t * 2;
        const longlong2* pc = (const longlong2*)((const long long*)ei + NEDGE) + (size_t)t * 2;
        longlong2 a = pr[0], b = pr[1];
        r[0] = (int)a.x; r[1] = (int)a.y; r[2] = (int)b.x; r[3] = (int)b.y;
        a = pc[0]; b = pc[1];
        c[0] = (int)a.x; c[1] = (int)a.y; c[2] = (int)b.x; c[3] = (int)b.y;
    } else {
        int4 v = ((const int4*)((const int*)ei))[t];
        r[0] = v.x; r[1] = v.y; r[2] = v.z; r[3] = v.w;
        v = ((const int4*)((const int*)ei + NEDGE))[t];
        c[0] = v.x; c[1] = v.y; c[2] = v.z; c[3] = v.w;
    }
    float4 w4 = ((const float4*)ew)[t];
    float wv[4] = {w4.x, w4.y, w4.z, w4.w};
    #pragma unroll
    for (int k = 0; k < 4; k++) {
        float nw = g_dinv[r[k]] * wv[k] * g_dinv[c[k]];
        int pos = g_ptrD[c[k]] + atomicAdd(&g_cntD[c[k]], 1);
        g_eD[pos] = make_int2(r[k], __float_as_int(nw));
    }
}

// ---------------- GEMM1: t = x[N,128] @ W1[128,32] ----------------
__global__ void gemm1_kernel(const float* __restrict__ A, const float* __restrict__ W,
                             float* __restrict__ out) {
    constexpr int K = FIN;
    constexpr int PAD = 4;
    __shared__ float sW[K * 32];
    __shared__ float sA[64 * (K + PAD)];
    int tid = threadIdx.x;        // 256 threads
    int rb = blockIdx.x * 64;

    for (int i = tid; i < K * 8; i += 256)
        ((float4*)sW)[i] = ((const float4*)W)[i];

    int tc = tid & 7;
    int trp = tid >> 3;
    int r0 = trp * 2, r1 = r0 + 1;
    float acc[2][4] = {};

    for (int i = tid; i < 64 * K / 4; i += 256) {
        int r = i / (K / 4);
        int c4 = i % (K / 4);
        float4 v = make_float4(0.f, 0.f, 0.f, 0.f);
        if (rb + r < NNODE)
            v = *(const float4*)(A + (size_t)(rb + r) * K + c4 * 4);
        *(float4*)(sA + r * (K + PAD) + c4 * 4) = v;
    }
    __syncthreads();
    #pragma unroll 8
    for (int k = 0; k < K; k++) {
        float a0 = sA[r0 * (K + PAD) + k];
        float a1 = sA[r1 * (K + PAD) + k];
        float4 w = ((const float4*)sW)[k * 8 + tc];
        acc[0][0] += a0 * w.x; acc[0][1] += a0 * w.y;
        acc[0][2] += a0 * w.z; acc[0][3] += a0 * w.w;
        acc[1][0] += a1 * w.x; acc[1][1] += a1 * w.y;
        acc[1][2] += a1 * w.z; acc[1][3] += a1 * w.w;
    }
    #pragma unroll
    for (int rr = 0; rr < 2; rr++) {
        int r = rb + r0 + rr;
        if (r < NNODE) {
            float4 v = make_float4(acc[rr][0], acc[rr][1], acc[rr][2], acc[rr][3]);
            *(float4*)(out + (size_t)r * 32 + tc * 4) = v;
        }
    }
}

// ---------------- aggregation: warp/node, 4 edges in flight (R6 layout) -----
// lane = (edge-group g = lane>>3, feature-quad q = lane&7)
// MODE 0: h = relu(agg + bias); write t_next = h @ Wn to tout
// MODE 1: write agg + bias (no relu) to hout
template <int MODE>
__global__ void agg_kernel(const float* __restrict__ tin,
                           const float* __restrict__ bias,
                           const float* __restrict__ Wn,
                           float* __restrict__ tout,
                           float* __restrict__ hout) {
    __shared__ float s_row[8][32];
    int warp = threadIdx.x >> 5, lane = threadIdx.x & 31;
    int w = blockIdx.x * 8 + warp;
    int q = lane & 7, g = lane >> 3;

    float wcol[32];
    if (MODE == 0) {
        #pragma unroll
        for (int f = 0; f < 32; f++) wcol[f] = Wn[f * 32 + lane];
    }
    if (w >= NNODE) return;

    const float4* tin4 = (const float4*)tin;
    int p0 = g_ptrD[w], p1 = g_ptrD[w + 1];
    float4 acc = make_float4(0.f, 0.f, 0.f, 0.f);
    if (g == 0) {                         // self-loop on edge-group 0
        float dv = g_dinv[w];
        float4 f4 = __ldg(&tin4[(size_t)w * 8 + q]);
        float s = dv * dv;
        acc.x = s * f4.x; acc.y = s * f4.y; acc.z = s * f4.z; acc.w = s * f4.w;
    }
    // each edge-group walks edges p0+g, p0+g+4, ... : 4 gathers in flight/warp
    for (int p = p0 + g; p < p1; p += 4) {
        int2 ev = __ldg(&g_eD[p]);        // 8-lane broadcast
        float ww = __int_as_float(ev.y);
        float4 f4 = __ldg(&tin4[(size_t)ev.x * 8 + q]);
        acc.x += ww * f4.x; acc.y += ww * f4.y;
        acc.z += ww * f4.z; acc.w += ww * f4.w;
    }
    // reduce across the 4 edge-groups (lanes q, q+8, q+16, q+24)
    #pragma unroll
    for (int o = 16; o >= 8; o >>= 1) {
        acc.x += __shfl_down_sync(0xffffffffu, acc.x, o);
        acc.y += __shfl_down_sync(0xffffffffu, acc.y, o);
        acc.z += __shfl_down_sync(0xffffffffu, acc.z, o);
        acc.w += __shfl_down_sync(0xffffffffu, acc.w, o);
    }
    if (g == 0) {
        const float4* b4 = (const float4*)bias;
        float4 bb = __ldg(&b4[q]);
        acc.x += bb.x; acc.y += bb.y; acc.z += bb.z; acc.w += bb.w;
        if (MODE == 0) {
            acc.x = fmaxf(acc.x, 0.f); acc.y = fmaxf(acc.y, 0.f);
            acc.z = fmaxf(acc.z, 0.f); acc.w = fmaxf(acc.w, 0.f);
            *(float4*)&s_row[warp][q * 4] = acc;
        } else {
            ((float4*)hout)[(size_t)w * 8 + q] = acc;
        }
    }
    if (MODE == 0) {
        __syncwarp();
        float o = 0.f;
        #pragma unroll
        for (int f = 0; f < 32; f++) o += s_row[warp][f] * wcol[f];
        tout[(size_t)w * 32 + lane] = o;
    }
}

// ---------------- mean pool (batch is sorted) ----------------
__global__ void pool_kernel(const float* __restrict__ h, const void* batch) {
    int gtid = blockIdx.x * blockDim.x + threadIdx.x;
    int w = gtid >> 5, lane = gtid & 31;
    int n0 = w * 32;
    if (n0 >= NNODE) return;
    int is64 = g_is64;
    int n1 = (n0 + 32 < NNODE) ? n0 + 32 : NNODE;
    float acc = 0.f; int curg = -1; int run = 0;
    for (int i = n0; i < n1; i++) {
        int gg = is64 ? (int)((const long long*)batch)[i] : ((const int*)batch)[i];
        if (gg != curg) {
            if (curg >= 0) {
                atomicAdd(&g_pool[curg * 32 + lane], acc);
                if (lane == 0) atomicAdd(&g_cntg[curg], (float)run);
            }
            curg = gg; acc = 0.f; run = 0;
        }
        acc += h[(size_t)i * 32 + lane];
        run++;
    }
    if (curg >= 0) {
        atomicAdd(&g_pool[curg * 32 + lane], acc);
        if (lane == 0) atomicAdd(&g_cntg[curg], (float)run);
    }
}

// ---------------- tiny MLP head, single block, smem-staged weights ----------
__global__ void mlp_kernel(const float* __restrict__ Wm0, const float* __restrict__ bm0,
                           const float* __restrict__ Wm1, const float* __restrict__ bm1,
                           const float* __restrict__ Wout, const float* __restrict__ bout,
                           float* __restrict__ out) {
    __shared__ float sg[NGRAPH * HDIM];
    __shared__ float sm0[NGRAPH * MHDIM];
    __shared__ float sm1[NGRAPH * MHDIM];
    __shared__ float sW0[HDIM * MHDIM];
    __shared__ float sW1[MHDIM * MHDIM];
    __shared__ float sWo[MHDIM * NCLS];
    int tid = threadIdx.x;      // 256
    for (int i = tid; i < HDIM * MHDIM; i += 256) sW0[i] = Wm0[i];
    for (int i = tid; i < MHDIM * MHDIM; i += 256) sW1[i] = Wm1[i];
    for (int i = tid; i < MHDIM * NCLS; i += 256) sWo[i] = Wout[i];
    for (int i = tid; i < NGRAPH * HDIM; i += 256) {
        int gg = i / HDIM;
        sg[i] = g_pool[i] / fmaxf(g_cntg[gg], 1.0f);
    }
    __syncthreads();
    for (int i = tid; i < NGRAPH * MHDIM; i += 256) {
        int gg = i / MHDIM, j = i % MHDIM;
        float s = bm0[j];
        #pragma unroll
        for (int f = 0; f < HDIM; f++) s += sg[gg * HDIM + f] * sW0[f * MHDIM + j];
        sm0[i] = fmaxf(s, 0.f);
    }
    __syncthreads();
    for (int i = tid; i < NGRAPH * MHDIM; i += 256) {
        int gg = i / MHDIM, j = i % MHDIM;
        float s = bm1[j];
        #pragma unroll
        for (int f = 0; f < MHDIM; f++) s += sm0[gg * MHDIM + f] * sW1[f * MHDIM + j];
        sm1[i] = fmaxf(s, 0.f);
    }
    __syncthreads();
    for (int i = tid; i < NGRAPH * NCLS; i += 256) {
        int gg = i / NCLS, cc = i % NCLS;
        float s = bout[cc];
        #pragma unroll
        for (int j = 0; j < MHDIM; j++) s += sm1[gg * MHDIM + j] * sWo[j * NCLS + cc];
        out[i] = s;
    }
}

// ---------------- launch ----------------
extern "C" void kernel_launch(void* const* d_in, const int* in_sizes, int n_in,
                              void* d_out, int out_size) {
    const float* x    = (const float*)d_in[0];
    const void*  ei   = d_in[1];
    const float* ew   = (const float*)d_in[2];
    const void*  batch= d_in[3];
    const float* W1   = (const float*)d_in[4];
    const float* b1   = (const float*)d_in[5];
    const float* W2   = (const float*)d_in[6];
    const float* b2   = (const float*)d_in[7];
    const float* W3   = (const float*)d_in[8];
    const float* b3   = (const float*)d_in[9];
    const float* Wm0  = (const float*)d_in[10];
    const float* bm0  = (const float*)d_in[11];
    const float* Wm1  = (const float*)d_in[12];
    const float* bm1  = (const float*)d_in[13];
    const float* Wout = (const float*)d_in[14];
    const float* bout = (const float*)d_in[15];
    float* out = (float*)d_out;

    float *tA, *tB, *h_ptr;
    cudaGetSymbolAddress((void**)&tA, g_tA);
    cudaGetSymbolAddress((void**)&tB, g_tB);
    cudaGetSymbolAddress((void**)&h_ptr, g_h);

    const int EB4 = (NEDGE / 4 + 255) / 256;     // 3125
    const int NB  = NBLK;                         // 391
    const int GB  = (NNODE + 63) / 64;            // 1563
    const int AB  = (NNODE + 7) / 8;              // 12500

    init_kernel<<<NB, 256>>>(ei);                            // 1
    hist_kernel<<<EB4, 256>>>(ei, ew);                       // 2
    scan_kernel<<<NB, 256>>>();                              // 3
    fill_kernel<<<EB4, 256>>>(ei, ew);                       // 4  <- ncu slot

    gemm1_kernel<<<GB, 256>>>(x, W1, tA);                    // 5
    agg_kernel<0><<<AB, 256>>>(tA, b1, W2, tB, nullptr);     // 6
    agg_kernel<0><<<AB, 256>>>(tB, b2, W3, tA, nullptr);     // 7
    agg_kernel<1><<<AB, 256>>>(tA, b3, nullptr, nullptr, h_ptr); // 8

    pool_kernel<<<NB, 256>>>(h_ptr, batch);                  // 9
    mlp_kernel<<<1, 256>>>(Wm0, bm0, Wm1, bm1, Wout, bout, out); // 10
}

// round 11
// speedup vs baseline: 1.1784x; 1.0666x over previous
#include <cuda_runtime.h>
#include <cuda_fp16.h>
#include <cstdint>

#define NNODE 100000
#define NEDGE 3200000
#define FIN   128
#define HDIM  32
#define MHDIM 64
#define NCLS  10
#define NGRAPH 64
#define NBLK  ((NNODE + 255) / 256)   // 391

// ---------------- device scratch (static, no allocation) ----------------
__device__ unsigned long long g_degCnt[NNODE];  // (count<<32) | fixed-point deg (2^20)
__device__ float    g_dinv[NNODE];
__device__ int      g_cntD[NNODE];
__device__ int      g_ptrD[NNODE + 1];
__device__ int2     g_eD[NEDGE];          // (src, dinv[src]*ew bits) packed
__device__ unsigned g_state[NBLK];        // decoupled-lookback states
__device__ __half2  g_tA[(size_t)NNODE * 16];  // fp16 feature tables (32 halves/row)
__device__ __half2  g_tB[(size_t)NNODE * 16];
__device__ float    g_h[(size_t)NNODE * HDIM];
__device__ float    g_pool[NGRAPH * HDIM];
__device__ float    g_cntg[NGRAPH];
__device__ int      g_is64;

__device__ __forceinline__ float4 unpack4(uint2 u) {
    __half2 h0 = *(__half2*)&u.x, h1 = *(__half2*)&u.y;
    float2 a = __half22float2(h0), b = __half22float2(h1);
    return make_float4(a.x, a.y, b.x, b.y);
}

// ---------------- init + dtype detect (fused, fully parallel) ----------------
__global__ void init_kernel(const void* ei) {
    int i = blockIdx.x * blockDim.x + threadIdx.x;
    if (i < NNODE) {
        g_degCnt[i] = (1ull << 20);   // count=0, deg=1.0 (self-loop weight)
        g_cntD[i] = 0;
    }
    if (i < NBLK) g_state[i] = 0u;
    if (i < NGRAPH * HDIM) g_pool[i] = 0.0f;
    if (i < NGRAPH) g_cntg[i] = 0.0f;
    if (i == 0) g_ptrD[NNODE] = NEDGE;
    if (blockIdx.x == 0 && threadIdx.x < 32) {
        const long long* p = (const long long*)ei;
        int bad = 0;
        #pragma unroll
        for (int k = 0; k < 4; k++) {
            long long v = p[(threadIdx.x * 4 + k) * 5 + 1];
            if (v < 0 || v >= NNODE) bad = 1;
        }
        unsigned m = __ballot_sync(0xffffffffu, bad);
        if (threadIdx.x == 0) g_is64 = (m == 0u);
    }
}

// ---- histogram: ONE packed 64-bit atomic per edge (count + fixed deg) ------
__global__ void hist_kernel(const void* ei, const float* __restrict__ ew) {
    int t = blockIdx.x * blockDim.x + threadIdx.x;   // 0 .. NEDGE/4-1
    if (t >= NEDGE / 4) return;
    int c0, c1, c2, c3;
    if (g_is64) {
        const longlong2* p = (const longlong2*)((const long long*)ei + NEDGE) + (size_t)t * 2;
        longlong2 a = p[0], b = p[1];
        c0 = (int)a.x; c1 = (int)a.y; c2 = (int)b.x; c3 = (int)b.y;
    } else {
        int4 v = ((const int4*)((const int*)ei + NEDGE))[t];
        c0 = v.x; c1 = v.y; c2 = v.z; c3 = v.w;
    }
    float4 w = ((const float4*)ew)[t];
    atomicAdd(&g_degCnt[c0], (1ull << 32) + (unsigned long long)(w.x * 1048576.0f + 0.5f));
    atomicAdd(&g_degCnt[c1], (1ull << 32) + (unsigned long long)(w.y * 1048576.0f + 0.5f));
    atomicAdd(&g_degCnt[c2], (1ull << 32) + (unsigned long long)(w.z * 1048576.0f + 0.5f));
    atomicAdd(&g_degCnt[c3], (1ull << 32) + (unsigned long long)(w.w * 1048576.0f + 0.5f));
}

// ---------------- single-pass scan: decoupled lookback ----------------
__global__ void scan_kernel() {
    __shared__ int ws[8];
    __shared__ int s_prefix;
    int b = blockIdx.x, tid = threadIdx.x;
    int i = b * 256 + tid;
    int v = 0; float deg = 1.0f;
    if (i < NNODE) {
        unsigned long long pk = g_degCnt[i];
        v = (int)(pk >> 32);
        deg = (float)(pk & 0xffffffffull) * (1.0f / 1048576.0f);
    }
    int lane = tid & 31, wid = tid >> 5;
    int x = v;
    #pragma unroll
    for (int o = 1; o < 32; o <<= 1) {
        int y = __shfl_up_sync(0xffffffffu, x, o);
        if (lane >= o) x += y;
    }
    if (lane == 31) ws[wid] = x;
    __syncthreads();
    if (wid == 0 && lane < 8) {
        int s = ws[lane];
        #pragma unroll
        for (int o = 1; o < 8; o <<= 1) {
            int y = __shfl_up_sync(0x000000ffu, s, o);
            if (lane >= o) s += y;
        }
        ws[lane] = s;
    }
    __syncthreads();
    int woff = (wid > 0) ? ws[wid - 1] : 0;
    int total = ws[7];

    if (wid == 0) {
        if (b == 0) {
            if (lane == 0) {
                atomicExch(&g_state[0], (2u << 30) | (unsigned)total);
                s_prefix = 0;
            }
        } else {
            if (lane == 0) atomicExch(&g_state[b], (1u << 30) | (unsigned)total);
            int prefix = 0, base = b - 1;
            bool done = false;
            while (!done) {
                int idx = base - lane;
                unsigned s = (2u << 30);
                for (;;) {
                    if (idx >= 0) s = *(volatile unsigned*)&g_state[idx];
                    unsigned ready = __ballot_sync(0xffffffffu, (s >> 30) != 0u);
                    if (ready == 0xffffffffu) break;
                }
                unsigned m2 = __ballot_sync(0xffffffffu, (s >> 30) == 2u);
                int stop = (m2 != 0u) ? (__ffs(m2) - 1) : 32;
                int val = (idx >= 0 && lane <= stop) ? (int)(s & 0x3FFFFFFFu) : 0;
                #pragma unroll
                for (int o = 16; o > 0; o >>= 1)
                    val += __shfl_down_sync(0xffffffffu, val, o);
                if (lane == 0) prefix += val;
                done = (m2 != 0u);
                base -= 32;
            }
            if (lane == 0) {
                atomicExch(&g_state[b], (2u << 30) | (unsigned)(prefix + total));
                s_prefix = prefix;
            }
        }
    }
    __syncthreads();
    int excl = s_prefix + woff + x - v;
    if (i < NNODE) {
        g_ptrD[i] = excl;
        g_dinv[i] = rsqrtf(deg);   // deg >= 1 always
    }
}

// ---- fill CSR-by-destination, packed (src, dinv[src]*ew) -------------------
// dinv[dst] is factored out and applied in agg (it is constant per segment).
__global__ void fill_kernel(const void* ei, const float* __restrict__ ew) {
    int t = blockIdx.x * blockDim.x + threadIdx.x;   // 0 .. NEDGE/4-1
    if (t >= NEDGE / 4) return;
    int r[4], c[4];
    if (g_is64) {
        const longlong2* pr = (const longlong2*)((const long long*)ei) + (size_t)t * 2;
        const longlong2* pc = (const longlong2*)((const long long*)ei + NEDGE) + (size_t)t * 2;
        longlong2 a = pr[0], b = pr[1];
        r[0] = (int)a.x; r[1] = (int)a.y; r[2] = (int)b.x; r[3] = (int)b.y;
        a = pc[0]; b = pc[1];
        c[0] = (int)a.x; c[1] = (int)a.y; c[2] = (int)b.x; c[3] = (int)b.y;
    } else {
        int4 v = ((const int4*)((const int*)ei))[t];
        r[0] = v.x; r[1] = v.y; r[2] = v.z; r[3] = v.w;
        v = ((const int4*)((const int*)ei + NEDGE))[t];
        c[0] = v.x; c[1] = v.y; c[2] = v.z; c[3] = v.w;
    }
    float4 w4 = ((const float4*)ew)[t];
    float wv[4] = {w4.x, w4.y, w4.z, w4.w};
    #pragma unroll
    for (int k = 0; k < 4; k++) {
        float nw = __ldg(&g_dinv[r[k]]) * wv[k];
        int pos = g_ptrD[c[k]] + atomicAdd(&g_cntD[c[k]], 1);
        g_eD[pos] = make_int2(r[k], __float_as_int(nw));
    }
}

// ---------------- GEMM1: t = x[N,128] @ W1[128,32] -> fp16 ----------------
__global__ void gemm1_kernel(const float* __restrict__ A, const float* __restrict__ W,
                             __half2* __restrict__ out16) {
    constexpr int K = FIN;
    constexpr int PAD = 4;
    __shared__ float sW[K * 32];
    __shared__ float sA[64 * (K + PAD)];
    int tid = threadIdx.x;        // 256 threads
    int rb = blockIdx.x * 64;

    for (int i = tid; i < K * 8; i += 256)
        ((float4*)sW)[i] = ((const float4*)W)[i];

    int tc = tid & 7;
    int trp = tid >> 3;
    int r0 = trp * 2, r1 = r0 + 1;
    float acc[2][4] = {};

    for (int i = tid; i < 64 * K / 4; i += 256) {
        int r = i / (K / 4);
        int c4 = i % (K / 4);
        float4 v = make_float4(0.f, 0.f, 0.f, 0.f);
        if (rb + r < NNODE)
            v = *(const float4*)(A + (size_t)(rb + r) * K + c4 * 4);
        *(float4*)(sA + r * (K + PAD) + c4 * 4) = v;
    }
    __syncthreads();
    #pragma unroll 8
    for (int k = 0; k < K; k++) {
        float a0 = sA[r0 * (K + PAD) + k];
        float a1 = sA[r1 * (K + PAD) + k];
        float4 w = ((const float4*)sW)[k * 8 + tc];
        acc[0][0] += a0 * w.x; acc[0][1] += a0 * w.y;
        acc[0][2] += a0 * w.z; acc[0][3] += a0 * w.w;
        acc[1][0] += a1 * w.x; acc[1][1] += a1 * w.y;
        acc[1][2] += a1 * w.z; acc[1][3] += a1 * w.w;
    }
    #pragma unroll
    for (int rr = 0; rr < 2; rr++) {
        int r = rb + r0 + rr;
        if (r < NNODE) {
            out16[(size_t)r * 16 + tc * 2]     = __floats2half2_rn(acc[rr][0], acc[rr][1]);
            out16[(size_t)r * 16 + tc * 2 + 1] = __floats2half2_rn(acc[rr][2], acc[rr][3]);
        }
    }
}

// ---------------- aggregation: warp/node, fp16 rows, 4 edges in flight ------
// lane = (edge-group g = lane>>3, feature-quad q = lane&7); lane loads 8B (4 halves)
// MODE 0: h = relu(dv*agg + bias); write t_next = h @ Wn as fp16 to tout
// MODE 1: write dv*agg + bias (no relu) as fp32 to hout
template <int MODE>
__global__ void agg_kernel(const __half2* __restrict__ tin,
                           const float* __restrict__ bias,
                           const float* __restrict__ Wn,
                           __half2* __restrict__ tout,
                           float* __restrict__ hout) {
    __shared__ float s_row[8][32];
    int warp = threadIdx.x >> 5, lane = threadIdx.x & 31;
    int w = blockIdx.x * 8 + warp;
    int q = lane & 7, g = lane >> 3;

    float wcol[32];
    if (MODE == 0) {
        #pragma unroll
        for (int f = 0; f < 32; f++) wcol[f] = Wn[f * 32 + lane];
    }
    if (w >= NNODE) return;

    const uint2* tin2 = (const uint2*)tin;   // 8 B = 4 halves per lane
    int p0 = g_ptrD[w], p1 = g_ptrD[w + 1];
    float dv = g_dinv[w];
    float4 acc = make_float4(0.f, 0.f, 0.f, 0.f);
    if (g == 0) {                 // self-loop: dv * t[w] (outer dv applied at end)
        float4 f4 = unpack4(__ldg(&tin2[(size_t)w * 8 + q]));
        acc.x = dv * f4.x; acc.y = dv * f4.y; acc.z = dv * f4.z; acc.w = dv * f4.w;
    }
    for (int p = p0 + g; p < p1; p += 4) {
        int2 ev = __ldg(&g_eD[p]);            // 8-lane broadcast
        float ww = __int_as_float(ev.y);      // dinv[src]*ew
        float4 f4 = unpack4(__ldg(&tin2[(size_t)ev.x * 8 + q]));
        acc.x += ww * f4.x; acc.y += ww * f4.y;
        acc.z += ww * f4.z; acc.w += ww * f4.w;
    }
    #pragma unroll
    for (int o = 16; o >= 8; o >>= 1) {
        acc.x += __shfl_down_sync(0xffffffffu, acc.x, o);
        acc.y += __shfl_down_sync(0xffffffffu, acc.y, o);
        acc.z += __shfl_down_sync(0xffffffffu, acc.z, o);
        acc.w += __shfl_down_sync(0xffffffffu, acc.w, o);
    }
    if (g == 0) {
        const float4* b4 = (const float4*)bias;
        float4 bb = __ldg(&b4[q]);
        acc.x = dv * acc.x + bb.x; acc.y = dv * acc.y + bb.y;
        acc.z = dv * acc.z + bb.z; acc.w = dv * acc.w + bb.w;
        if (MODE == 0) {
            acc.x = fmaxf(acc.x, 0.f); acc.y = fmaxf(acc.y, 0.f);
            acc.z = fmaxf(acc.z, 0.f); acc.w = fmaxf(acc.w, 0.f);
            *(float4*)&s_row[warp][q * 4] = acc;
        } else {
            ((float4*)hout)[(size_t)w * 8 + q] = acc;
        }
    }
    if (MODE == 0) {
        __syncwarp();
        float o = 0.f;
        #pragma unroll
        for (int f = 0; f < 32; f++) o += s_row[warp][f] * wcol[f];
        float oo = __shfl_down_sync(0xffffffffu, o, 1);
        if ((lane & 1) == 0)
            tout[(size_t)w * 16 + (lane >> 1)] = __floats2half2_rn(o, oo);
    }
}

// ---------------- mean pool (batch is sorted) ----------------
__global__ void pool_kernel(const float* __restrict__ h, const void* batch) {
    int gtid = blockIdx.x * blockDim.x + threadIdx.x;
    int w = gtid >> 5, lane = gtid & 31;
    int n0 = w * 32;
    if (n0 >= NNODE) return;
    int is64 = g_is64;
    int n1 = (n0 + 32 < NNODE) ? n0 + 32 : NNODE;
    float acc = 0.f; int curg = -1; int run = 0;
    for (int i = n0; i < n1; i++) {
        int gg = is64 ? (int)((const long long*)batch)[i] : ((const int*)batch)[i];
        if (gg != curg) {
            if (curg >= 0) {
                atomicAdd(&g_pool[curg * 32 + lane], acc);
                if (lane == 0) atomicAdd(&g_cntg[curg], (float)run);
            }
            curg = gg; acc = 0.f; run = 0;
        }
        acc += h[(size_t)i * 32 + lane];
        run++;
    }
    if (curg >= 0) {
        atomicAdd(&g_pool[curg * 32 + lane], acc);
        if (lane == 0) atomicAdd(&g_cntg[curg], (float)run);
    }
}

// ---------------- tiny MLP head, single block, smem-staged weights ----------
__global__ void mlp_kernel(const float* __restrict__ Wm0, const float* __restrict__ bm0,
                           const float* __restrict__ Wm1, const float* __restrict__ bm1,
                           const float* __restrict__ Wout, const float* __restrict__ bout,
                           float* __restrict__ out) {
    __shared__ float sg[NGRAPH * HDIM];
    __shared__ float sm0[NGRAPH * MHDIM];
    __shared__ float sm1[NGRAPH * MHDIM];
    __shared__ float sW0[HDIM * MHDIM];
    __shared__ float sW1[MHDIM * MHDIM];
    __shared__ float sWo[MHDIM * NCLS];
    int tid = threadIdx.x;      // 256
    for (int i = tid; i < HDIM * MHDIM; i += 256) sW0[i] = Wm0[i];
    for (int i = tid; i < MHDIM * MHDIM; i += 256) sW1[i] = Wm1[i];
    for (int i = tid; i < MHDIM * NCLS; i += 256) sWo[i] = Wout[i];
    for (int i = tid; i < NGRAPH * HDIM; i += 256) {
        int gg = i / HDIM;
        sg[i] = g_pool[i] / fmaxf(g_cntg[gg], 1.0f);
    }
    __syncthreads();
    for (int i = tid; i < NGRAPH * MHDIM; i += 256) {
        int gg = i / MHDIM, j = i % MHDIM;
        float s = bm0[j];
        #pragma unroll
        for (int f = 0; f < HDIM; f++) s += sg[gg * HDIM + f] * sW0[f * MHDIM + j];
        sm0[i] = fmaxf(s, 0.f);
    }
    __syncthreads();
    for (int i = tid; i < NGRAPH * MHDIM; i += 256) {
        int gg = i / MHDIM, j = i % MHDIM;
        float s = bm1[j];
        #pragma unroll
        for (int f = 0; f < MHDIM; f++) s += sm0[gg * MHDIM + f] * sW1[f * MHDIM + j];
        sm1[i] = fmaxf(s, 0.f);
    }
    __syncthreads();
    for (int i = tid; i < NGRAPH * NCLS; i += 256) {
        int gg = i / NCLS, cc = i % NCLS;
        float s = bout[cc];
        #pragma unroll
        for (int j = 0; j < MHDIM; j++) s += sm1[gg * MHDIM + j] * sWo[j * NCLS + cc];
        out[i] = s;
    }
}

// ---------------- launch ----------------
extern "C" void kernel_launch(void* const* d_in, const int* in_sizes, int n_in,
                              void* d_out, int out_size) {
    const float* x    = (const float*)d_in[0];
    const void*  ei   = d_in[1];
    const float* ew   = (const float*)d_in[2];
    const void*  batch= d_in[3];
    const float* W1   = (const float*)d_in[4];
    const float* b1   = (const float*)d_in[5];
    const float* W2   = (const float*)d_in[6];
    const float* b2   = (const float*)d_in[7];
    const float* W3   = (const float*)d_in[8];
    const float* b3   = (const float*)d_in[9];
    const float* Wm0  = (const float*)d_in[10];
    const float* bm0  = (const float*)d_in[11];
    const float* Wm1  = (const float*)d_in[12];
    const float* bm1  = (const float*)d_in[13];
    const float* Wout = (const float*)d_in[14];
    const float* bout = (const float*)d_in[15];
    float* out = (float*)d_out;

    __half2 *tA, *tB; float* h_ptr;
    cudaGetSymbolAddress((void**)&tA, g_tA);
    cudaGetSymbolAddress((void**)&tB, g_tB);
    cudaGetSymbolAddress((void**)&h_ptr, g_h);

    const int EB4 = (NEDGE / 4 + 255) / 256;     // 3125
    const int NB  = NBLK;                         // 391
    const int GB  = (NNODE + 63) / 64;            // 1563
    const int AB  = (NNODE + 7) / 8;              // 12500

    init_kernel<<<NB, 256>>>(ei);                            // 1
    hist_kernel<<<EB4, 256>>>(ei, ew);                       // 2
    scan_kernel<<<NB, 256>>>();                              // 3
    fill_kernel<<<EB4, 256>>>(ei, ew);                       // 4  <- ncu slot

    gemm1_kernel<<<GB, 256>>>(x, W1, tA);                    // 5
    agg_kernel<0><<<AB, 256>>>(tA, b1, W2, tB, nullptr);     // 6
    agg_kernel<0><<<AB, 256>>>(tB, b2, W3, tA, nullptr);     // 7
    agg_kernel<1><<<AB, 256>>>(tA, b3, nullptr, nullptr, h_ptr); // 8

    pool_kernel<<<NB, 256>>>(h_ptr, batch);                  // 9
    mlp_kernel<<<1, 256>>>(Wm0, bm0, Wm1, bm1, Wout, bout, out); // 10
}

// round 12
// speedup vs baseline: 1.3544x; 1.1494x over previous
#include <cuda_runtime.h>
#include <cuda_fp16.h>
#include <mma.h>
#include <cstdint>

using namespace nvcuda;

#define NNODE 100000
#define NEDGE 3200000
#define FIN   128
#define HDIM  32
#define MHDIM 64
#define NCLS  10
#define NGRAPH 64
#define NBLK  ((NNODE + 255) / 256)   // 391

// ---------------- device scratch (static, no allocation) ----------------
__device__ unsigned long long g_degCnt[NNODE];  // (count<<32) | fixed-point deg (2^20)
__device__ float    g_dinv[NNODE];
__device__ int      g_cntD[NNODE];
__device__ int      g_ptrD[NNODE + 1];
__device__ int2     g_eD[NEDGE];          // (src, dinv[src]*ew bits) packed
__device__ unsigned g_state[NBLK];        // decoupled-lookback states
__device__ __half2  g_tA[(size_t)NNODE * 16];  // fp16 feature tables (32 halves/row)
__device__ __half2  g_tB[(size_t)NNODE * 16];
__device__ float    g_pool[NGRAPH * HDIM];
__device__ float    g_cntg[NGRAPH];
__device__ int      g_is64;

__device__ __forceinline__ float4 unpack4(uint2 u) {
    __half2 h0 = *(__half2*)&u.x, h1 = *(__half2*)&u.y;
    float2 a = __half22float2(h0), b = __half22float2(h1);
    return make_float4(a.x, a.y, b.x, b.y);
}

// ---------------- init + dtype detect (fused, fully parallel) ----------------
__global__ void init_kernel(const void* ei) {
    int i = blockIdx.x * blockDim.x + threadIdx.x;
    if (i < NNODE) {
        g_degCnt[i] = (1ull << 20);   // count=0, deg=1.0 (self-loop weight)
        g_cntD[i] = 0;
    }
    if (i < NBLK) g_state[i] = 0u;
    if (i < NGRAPH * HDIM) g_pool[i] = 0.0f;
    if (i < NGRAPH) g_cntg[i] = 0.0f;
    if (i == 0) g_ptrD[NNODE] = NEDGE;
    if (blockIdx.x == 0 && threadIdx.x < 32) {
        const long long* p = (const long long*)ei;
        int bad = 0;
        #pragma unroll
        for (int k = 0; k < 4; k++) {
            long long v = p[(threadIdx.x * 4 + k) * 5 + 1];
            if (v < 0 || v >= NNODE) bad = 1;
        }
        unsigned m = __ballot_sync(0xffffffffu, bad);
        if (threadIdx.x == 0) g_is64 = (m == 0u);
    }
}

// ---- histogram: ONE packed 64-bit atomic per edge (count + fixed deg) ------
__global__ void hist_kernel(const void* ei, const float* __restrict__ ew) {
    int t = blockIdx.x * blockDim.x + threadIdx.x;   // 0 .. NEDGE/4-1
    if (t >= NEDGE / 4) return;
    int c0, c1, c2, c3;
    if (g_is64) {
        const longlong2* p = (const longlong2*)((const long long*)ei + NEDGE) + (size_t)t * 2;
        longlong2 a = p[0], b = p[1];
        c0 = (int)a.x; c1 = (int)a.y; c2 = (int)b.x; c3 = (int)b.y;
    } else {
        int4 v = ((const int4*)((const int*)ei + NEDGE))[t];
        c0 = v.x; c1 = v.y; c2 = v.z; c3 = v.w;
    }
    float4 w = ((const float4*)ew)[t];
    atomicAdd(&g_degCnt[c0], (1ull << 32) + (unsigned long long)(w.x * 1048576.0f + 0.5f));
    atomicAdd(&g_degCnt[c1], (1ull << 32) + (unsigned long long)(w.y * 1048576.0f + 0.5f));
    atomicAdd(&g_degCnt[c2], (1ull << 32) + (unsigned long long)(w.z * 1048576.0f + 0.5f));
    atomicAdd(&g_degCnt[c3], (1ull << 32) + (unsigned long long)(w.w * 1048576.0f + 0.5f));
}

// ---------------- single-pass scan: decoupled lookback ----------------
__global__ void scan_kernel() {
    __shared__ int ws[8];
    __shared__ int s_prefix;
    int b = blockIdx.x, tid = threadIdx.x;
    int i = b * 256 + tid;
    int v = 0; float deg = 1.0f;
    if (i < NNODE) {
        unsigned long long pk = g_degCnt[i];
        v = (int)(pk >> 32);
        deg = (float)(pk & 0xffffffffull) * (1.0f / 1048576.0f);
    }
    int lane = tid & 31, wid = tid >> 5;
    int x = v;
    #pragma unroll
    for (int o = 1; o < 32; o <<= 1) {
        int y = __shfl_up_sync(0xffffffffu, x, o);
        if (lane >= o) x += y;
    }
    if (lane == 31) ws[wid] = x;
    __syncthreads();
    if (wid == 0 && lane < 8) {
        int s = ws[lane];
        #pragma unroll
        for (int o = 1; o < 8; o <<= 1) {
            int y = __shfl_up_sync(0x000000ffu, s, o);
            if (lane >= o) s += y;
        }
        ws[lane] = s;
    }
    __syncthreads();
    int woff = (wid > 0) ? ws[wid - 1] : 0;
    int total = ws[7];

    if (wid == 0) {
        if (b == 0) {
            if (lane == 0) {
                atomicExch(&g_state[0], (2u << 30) | (unsigned)total);
                s_prefix = 0;
            }
        } else {
            if (lane == 0) atomicExch(&g_state[b], (1u << 30) | (unsigned)total);
            int prefix = 0, base = b - 1;
            bool done = false;
            while (!done) {
                int idx = base - lane;
                unsigned s = (2u << 30);
                for (;;) {
                    if (idx >= 0) s = *(volatile unsigned*)&g_state[idx];
                    unsigned ready = __ballot_sync(0xffffffffu, (s >> 30) != 0u);
                    if (ready == 0xffffffffu) break;
                }
                unsigned m2 = __ballot_sync(0xffffffffu, (s >> 30) == 2u);
                int stop = (m2 != 0u) ? (__ffs(m2) - 1) : 32;
                int val = (idx >= 0 && lane <= stop) ? (int)(s & 0x3FFFFFFFu) : 0;
                #pragma unroll
                for (int o = 16; o > 0; o >>= 1)
                    val += __shfl_down_sync(0xffffffffu, val, o);
                if (lane == 0) prefix += val;
                done = (m2 != 0u);
                base -= 32;
            }
            if (lane == 0) {
                atomicExch(&g_state[b], (2u << 30) | (unsigned)(prefix + total));
                s_prefix = prefix;
            }
        }
    }
    __syncthreads();
    int excl = s_prefix + woff + x - v;
    if (i < NNODE) {
        g_ptrD[i] = excl;
        g_dinv[i] = rsqrtf(deg);   // deg >= 1 always
    }
}

// ---- fill CSR-by-destination, packed (src, dinv[src]*ew) -------------------
__global__ void fill_kernel(const void* ei, const float* __restrict__ ew) {
    int t = blockIdx.x * blockDim.x + threadIdx.x;   // 0 .. NEDGE/4-1
    if (t >= NEDGE / 4) return;
    int r[4], c[4];
    if (g_is64) {
        const longlong2* pr = (const longlong2*)((const long long*)ei) + (size_t)t * 2;
        const longlong2* pc = (const longlong2*)((const long long*)ei + NEDGE) + (size_t)t * 2;
        longlong2 a = pr[0], b = pr[1];
        r[0] = (int)a.x; r[1] = (int)a.y; r[2] = (int)b.x; r[3] = (int)b.y;
        a = pc[0]; b = pc[1];
        c[0] = (int)a.x; c[1] = (int)a.y; c[2] = (int)b.x; c[3] = (int)b.y;
    } else {
        int4 v = ((const int4*)((const int*)ei))[t];
        r[0] = v.x; r[1] = v.y; r[2] = v.z; r[3] = v.w;
        v = ((const int4*)((const int*)ei + NEDGE))[t];
        c[0] = v.x; c[1] = v.y; c[2] = v.z; c[3] = v.w;
    }
    float4 w4 = ((const float4*)ew)[t];
    float wv[4] = {w4.x, w4.y, w4.z, w4.w};
    #pragma unroll
    for (int k = 0; k < 4; k++) {
        float nw = __ldg(&g_dinv[r[k]]) * wv[k];
        int pos = g_ptrD[c[k]] + atomicAdd(&g_cntD[c[k]], 1);
        g_eD[pos] = make_int2(r[k], __float_as_int(nw));
    }
}

// ------------- GEMM1 via WMMA: t = x[N,128] @ W1[128,32] -> fp16 ------------
// 128 rows/block, 8 warps: warp w owns row-tile w (16 rows), 2 col-tiles.
#define LDA 136   // padded halves per row (mult of 8)
#define LDB 40
__global__ void gemm1_kernel(const float* __restrict__ A, const float* __restrict__ W,
                             __half2* __restrict__ out16) {
    __shared__ __half sA[128 * LDA];
    __shared__ __half sW[FIN * LDB];
    __shared__ float  sC[128 * 32];
    int tid = threadIdx.x;        // 256
    int wid = tid >> 5;
    int rb = blockIdx.x * 128;

    // load W (128x32 fp32) -> fp16 smem
    for (int idx = tid; idx < FIN * 32 / 4; idx += 256) {
        int r = idx >> 3, c4 = (idx & 7) * 4;
        float4 v = *(const float4*)(W + r * 32 + c4);
        __half2 h0 = __floats2half2_rn(v.x, v.y);
        __half2 h1 = __floats2half2_rn(v.z, v.w);
        *(__half2*)&sW[r * LDB + c4]     = h0;
        *(__half2*)&sW[r * LDB + c4 + 2] = h1;
    }
    // load x tile (128x128 fp32) -> fp16 smem
    for (int idx = tid; idx < 128 * FIN / 4; idx += 256) {
        int r = idx >> 5, c4 = (idx & 31) * 4;
        float4 v = make_float4(0.f, 0.f, 0.f, 0.f);
        if (rb + r < NNODE)
            v = *(const float4*)(A + (size_t)(rb + r) * FIN + c4);
        __half2 h0 = __floats2half2_rn(v.x, v.y);
        __half2 h1 = __floats2half2_rn(v.z, v.w);
        *(__half2*)&sA[r * LDA + c4]     = h0;
        *(__half2*)&sA[r * LDA + c4 + 2] = h1;
    }
    __syncthreads();

    wmma::fragment<wmma::accumulator, 16, 16, 16, float> c0, c1;
    wmma::fill_fragment(c0, 0.0f);
    wmma::fill_fragment(c1, 0.0f);
    #pragma unroll
    for (int k = 0; k < FIN; k += 16) {
        wmma::fragment<wmma::matrix_a, 16, 16, 16, __half, wmma::row_major> a;
        wmma::fragment<wmma::matrix_b, 16, 16, 16, __half, wmma::row_major> b0, b1;
        wmma::load_matrix_sync(a, &sA[wid * 16 * LDA + k], LDA);
        wmma::load_matrix_sync(b0, &sW[k * LDB], LDB);
        wmma::load_matrix_sync(b1, &sW[k * LDB + 16], LDB);
        wmma::mma_sync(c0, a, b0, c0);
        wmma::mma_sync(c1, a, b1, c1);
    }
    wmma::store_matrix_sync(&sC[wid * 16 * 32], c0, 32, wmma::mem_row_major);
    wmma::store_matrix_sync(&sC[wid * 16 * 32 + 16], c1, 32, wmma::mem_row_major);
    __syncthreads();

    // write fp16 table
    for (int idx = tid; idx < 128 * 16; idx += 256) {
        int r = idx >> 4, h2 = idx & 15;
        if (rb + r < NNODE)
            out16[(size_t)(rb + r) * 16 + h2] =
                __floats2half2_rn(sC[r * 32 + h2 * 2], sC[r * 32 + h2 * 2 + 1]);
    }
}

// ---------------- aggregation: warp/node, fp16 rows, 4 edges in flight ------
// MODE 0: h = relu(dv*agg + bias); t_next = h @ Wn -> fp16 tout
// MODE 1: h = dv*agg + bias; fused mean-pool accumulation into g_pool
template <int MODE>
__global__ void agg_kernel(const __half2* __restrict__ tin,
                           const float* __restrict__ bias,
                           const float* __restrict__ Wn,
                           __half2* __restrict__ tout,
                           const void* __restrict__ batch) {
    __shared__ float s_row[8][32];
    int warp = threadIdx.x >> 5, lane = threadIdx.x & 31;
    int w = blockIdx.x * 8 + warp;   // AB*8 == NNODE exactly: always valid
    int q = lane & 7, g = lane >> 3;

    float wcol[32];
    if (MODE == 0) {
        #pragma unroll
        for (int f = 0; f < 32; f++) wcol[f] = Wn[f * 32 + lane];
    }

    const uint2* tin2 = (const uint2*)tin;
    int p0 = g_ptrD[w], p1 = g_ptrD[w + 1];
    float dv = g_dinv[w];
    float4 acc = make_float4(0.f, 0.f, 0.f, 0.f);
    if (g == 0) {
        float4 f4 = unpack4(__ldg(&tin2[(size_t)w * 8 + q]));
        acc.x = dv * f4.x; acc.y = dv * f4.y; acc.z = dv * f4.z; acc.w = dv * f4.w;
    }
    for (int p = p0 + g; p < p1; p += 4) {
        int2 ev = __ldg(&g_eD[p]);
        float ww = __int_as_float(ev.y);
        float4 f4 = unpack4(__ldg(&tin2[(size_t)ev.x * 8 + q]));
        acc.x += ww * f4.x; acc.y += ww * f4.y;
        acc.z += ww * f4.z; acc.w += ww * f4.w;
    }
    #pragma unroll
    for (int o = 16; o >= 8; o >>= 1) {
        acc.x += __shfl_down_sync(0xffffffffu, acc.x, o);
        acc.y += __shfl_down_sync(0xffffffffu, acc.y, o);
        acc.z += __shfl_down_sync(0xffffffffu, acc.z, o);
        acc.w += __shfl_down_sync(0xffffffffu, acc.w, o);
    }
    if (g == 0) {
        const float4* b4 = (const float4*)bias;
        float4 bb = __ldg(&b4[q]);
        acc.x = dv * acc.x + bb.x; acc.y = dv * acc.y + bb.y;
        acc.z = dv * acc.z + bb.z; acc.w = dv * acc.w + bb.w;
        if (MODE == 0) {
            acc.x = fmaxf(acc.x, 0.f); acc.y = fmaxf(acc.y, 0.f);
            acc.z = fmaxf(acc.z, 0.f); acc.w = fmaxf(acc.w, 0.f);
        }
        *(float4*)&s_row[warp][q * 4] = acc;
    }
    if (MODE == 0) {
        __syncwarp();
        float o = 0.f;
        #pragma unroll
        for (int f = 0; f < 32; f++) o += s_row[warp][f] * wcol[f];
        float oo = __shfl_down_sync(0xffffffffu, o, 1);
        if ((lane & 1) == 0)
            tout[(size_t)w * 16 + (lane >> 1)] = __floats2half2_rn(o, oo);
    } else {
        // fused mean-pool accumulation (batch sorted; 8 nodes per block)
        __syncthreads();
        int base = blockIdx.x * 8;
        int is64 = g_is64;
        int gfirst = is64 ? (int)((const long long*)batch)[base]
                          : ((const int*)batch)[base];
        int glast  = is64 ? (int)((const long long*)batch)[base + 7]
                          : ((const int*)batch)[base + 7];
        if (gfirst == glast) {
            if (threadIdx.x < 32) {
                float s = 0.f;
                #pragma unroll
                for (int n = 0; n < 8; n++) s += s_row[n][threadIdx.x];
                atomicAdd(&g_pool[gfirst * 32 + threadIdx.x], s);
                if (threadIdx.x == 0) atomicAdd(&g_cntg[gfirst], 8.0f);
            }
        } else {
            int n = threadIdx.x >> 5, f = threadIdx.x & 31;
            int gn = is64 ? (int)((const long long*)batch)[base + n]
                          : ((const int*)batch)[base + n];
            atomicAdd(&g_pool[gn * 32 + f], s_row[n][f]);
            if (f == 0) atomicAdd(&g_cntg[gn], 1.0f);
        }
    }
}

// ---------------- tiny MLP head, single block, smem-staged weights ----------
__global__ void mlp_kernel(const float* __restrict__ Wm0, const float* __restrict__ bm0,
                           const float* __restrict__ Wm1, const float* __restrict__ bm1,
                           const float* __restrict__ Wout, const float* __restrict__ bout,
                           float* __restrict__ out) {
    __shared__ float sg[NGRAPH * HDIM];
    __shared__ float sm0[NGRAPH * MHDIM];
    __shared__ float sm1[NGRAPH * MHDIM];
    __shared__ float sW0[HDIM * MHDIM];
    __shared__ float sW1[MHDIM * MHDIM];
    __shared__ float sWo[MHDIM * NCLS];
    int tid = threadIdx.x;      // 256
    for (int i = tid; i < HDIM * MHDIM; i += 256) sW0[i] = Wm0[i];
    for (int i = tid; i < MHDIM * MHDIM; i += 256) sW1[i] = Wm1[i];
    for (int i = tid; i < MHDIM * NCLS; i += 256) sWo[i] = Wout[i];
    for (int i = tid; i < NGRAPH * HDIM; i += 256) {
        int gg = i / HDIM;
        sg[i] = g_pool[i] / fmaxf(g_cntg[gg], 1.0f);
    }
    __syncthreads();
    for (int i = tid; i < NGRAPH * MHDIM; i += 256) {
        int gg = i / MHDIM, j = i % MHDIM;
        float s = bm0[j];
        #pragma unroll
        for (int f = 0; f < HDIM; f++) s += sg[gg * HDIM + f] * sW0[f * MHDIM + j];
        sm0[i] = fmaxf(s, 0.f);
    }
    __syncthreads();
    for (int i = tid; i < NGRAPH * MHDIM; i += 256) {
        int gg = i / MHDIM, j = i % MHDIM;
        float s = bm1[j];
        #pragma unroll
        for (int f = 0; f < MHDIM; f++) s += sm0[gg * MHDIM + f] * sW1[f * MHDIM + j];
        sm1[i] = fmaxf(s, 0.f);
    }
    __syncthreads();
    for (int i = tid; i < NGRAPH * NCLS; i += 256) {
        int gg = i / NCLS, cc = i % NCLS;
        float s = bout[cc];
        #pragma unroll
        for (int j = 0; j < MHDIM; j++) s += sm1[gg * MHDIM + j] * sWo[j * NCLS + cc];
        out[i] = s;
    }
}

// ---------------- launch ----------------
extern "C" void kernel_launch(void* const* d_in, const int* in_sizes, int n_in,
                              void* d_out, int out_size) {
    const float* x    = (const float*)d_in[0];
    const void*  ei   = d_in[1];
    const float* ew   = (const float*)d_in[2];
    const void*  batch= d_in[3];
    const float* W1   = (const float*)d_in[4];
    const float* b1   = (const float*)d_in[5];
    const float* W2   = (const float*)d_in[6];
    const float* b2   = (const float*)d_in[7];
    const float* W3   = (const float*)d_in[8];
    const float* b3   = (const float*)d_in[9];
    const float* Wm0  = (const float*)d_in[10];
    const float* bm0  = (const float*)d_in[11];
    const float* Wm1  = (const float*)d_in[12];
    const float* bm1  = (const float*)d_in[13];
    const float* Wout = (const float*)d_in[14];
    const float* bout = (const float*)d_in[15];
    float* out = (float*)d_out;

    __half2 *tA, *tB;
    cudaGetSymbolAddress((void**)&tA, g_tA);
    cudaGetSymbolAddress((void**)&tB, g_tB);

    const int EB4 = (NEDGE / 4 + 255) / 256;     // 3125
    const int NB  = NBLK;                         // 391
    const int GB  = (NNODE + 127) / 128;          // 782
    const int AB  = NNODE / 8;                    // 12500 (exact)

    init_kernel<<<NB, 256>>>(ei);                            // 1
    hist_kernel<<<EB4, 256>>>(ei, ew);                       // 2
    scan_kernel<<<NB, 256>>>();                              // 3
    fill_kernel<<<EB4, 256>>>(ei, ew);                       // 4  <- ncu slot

    gemm1_kernel<<<GB, 256>>>(x, W1, tA);                    // 5
    agg_kernel<0><<<AB, 256>>>(tA, b1, W2, tB, nullptr);     // 6
    agg_kernel<0><<<AB, 256>>>(tB, b2, W3, tA, nullptr);     // 7
    agg_kernel<1><<<AB, 256>>>(tA, b3, nullptr, nullptr, batch); // 8 (agg+pool)

    mlp_kernel<<<1, 256>>>(Wm0, bm0, Wm1, bm1, Wout, bout, out); // 9
}